// round 2
// baseline (speedup 1.0000x reference)
#include <cuda_runtime.h>

#define NTOK 65536
#define CDIM 180
#define NH 6
#define HD 30
#define QKVC 540

typedef unsigned long long u64;

// ---- packed fp32x2 helpers (Blackwell f32x2 pipe; exact fp32 math) ----
__device__ __forceinline__ u64 pk2(float lo, float hi) {
    u64 r; asm("mov.b64 %0,{%1,%2};" : "=l"(r) : "f"(lo), "f"(hi)); return r;
}
__device__ __forceinline__ void upk2(u64 v, float& lo, float& hi) {
    asm("mov.b64 {%0,%1},%2;" : "=f"(lo), "=f"(hi) : "l"(v));
}
__device__ __forceinline__ void fma2(u64& d, u64 a, u64 b) {
    asm("fma.rn.f32x2 %0,%1,%2,%0;" : "+l"(d) : "l"(a), "l"(b));
}
__device__ __forceinline__ void mul2(u64& d, u64 a) {
    asm("mul.rn.f32x2 %0,%0,%1;" : "+l"(d) : "l"(a));
}

// Scratch (device globals — no allocation allowed)
__device__ float g_xn[(size_t)NTOK * CDIM];
__device__ float g_qkv[(size_t)NTOK * QKVC];   // [tok][0:180 q | 180:360 k | 360:540 v]
__device__ float g_att[(size_t)NTOK * CDIM];

// ---------------- LayerNorm: one warp per row ----------------
__global__ void ln_kernel(const float* __restrict__ x, const float* __restrict__ w,
                          const float* __restrict__ b, float* __restrict__ out) {
    int row  = blockIdx.x * 8 + (threadIdx.x >> 5);
    int lane = threadIdx.x & 31;
    const float* xr = x + (size_t)row * CDIM;
    float v[6];
    float s = 0.f, s2 = 0.f;
#pragma unroll
    for (int i = 0; i < 6; i++) {
        int d = lane + 32 * i;
        float val = (d < CDIM) ? xr[d] : 0.f;
        v[i] = val; s += val; s2 += val * val;
    }
#pragma unroll
    for (int o = 16; o; o >>= 1) {
        s  += __shfl_xor_sync(0xffffffffu, s, o);
        s2 += __shfl_xor_sync(0xffffffffu, s2, o);
    }
    float mu  = s * (1.f / CDIM);
    float var = s2 * (1.f / CDIM) - mu * mu;
    float rs  = rsqrtf(var + 1e-5f);
    float* orow = out + (size_t)row * CDIM;
#pragma unroll
    for (int i = 0; i < 6; i++) {
        int d = lane + 32 * i;
        if (d < CDIM) orow[d] = (v[i] - mu) * rs * w[d] + b[d];
    }
}

// ---------------- fp32x2 GEMM: C[M,N] = A[M,180] @ B[180,N] + bias (+res) ----------------
// 128x64 tile, BK=20 (10 k-pairs), 256 threads, 8x4 microtile, f32x2 accumulate over k-pairs.
__global__ __launch_bounds__(256) void gemm_kernel(
    const float* __restrict__ A, const float* __restrict__ B,
    const float* __restrict__ bias, const float* __restrict__ res,
    float* __restrict__ C, int N, int ldc) {
    __shared__ u64 As2[128][10];   // [row][k-pair]
    __shared__ u64 Bs2[10][64];    // [k-pair][col]
    int tx = threadIdx.x, ty = threadIdx.y;
    int li = ty * 16 + tx;
    int rowbase = blockIdx.y * 128;
    int nbase   = blockIdx.x * 64;
    u64 acc[8][4] = {};
    for (int k0 = 0; k0 < 180; k0 += 20) {
#pragma unroll
        for (int e = 0; e < 5; e++) {               // 1280 u64 A elements
            int idx = li + e * 256;
            int r = idx / 10, kk2 = idx - r * 10;
            As2[r][kk2] = *(const u64*)&A[(size_t)(rowbase + r) * 180 + k0 + 2 * kk2];
        }
#pragma unroll
        for (int e = 0; e < 3; e++) {               // 640 u64 B elements
            int idx = li + e * 256;
            if (idx < 640) {
                int kk2 = idx >> 6, cb = idx & 63;
                int col = nbase + cb;
                Bs2[kk2][cb] = (col < N)
                    ? pk2(B[(size_t)(k0 + 2 * kk2) * N + col],
                          B[(size_t)(k0 + 2 * kk2 + 1) * N + col])
                    : 0ULL;
            }
        }
        __syncthreads();
#pragma unroll
        for (int kk2 = 0; kk2 < 10; kk2++) {
            u64 a2[8], b2[4];
#pragma unroll
            for (int i = 0; i < 8; i++) a2[i] = As2[ty * 8 + i][kk2];
#pragma unroll
            for (int j = 0; j < 4; j++) b2[j] = Bs2[kk2][tx * 4 + j];
#pragma unroll
            for (int i = 0; i < 8; i++)
#pragma unroll
                for (int j = 0; j < 4; j++)
                    fma2(acc[i][j], a2[i], b2[j]);
        }
        __syncthreads();
    }
    int col = nbase + tx * 4;
    if (col < N) {                                   // tile/N boundaries are multiples of 4
        float4 bv = *(const float4*)&bias[col];
#pragma unroll
        for (int i = 0; i < 8; i++) {
            int row = rowbase + ty * 8 + i;
            float lo, hi; float4 o;
            upk2(acc[i][0], lo, hi); o.x = lo + hi + bv.x;
            upk2(acc[i][1], lo, hi); o.y = lo + hi + bv.y;
            upk2(acc[i][2], lo, hi); o.z = lo + hi + bv.z;
            upk2(acc[i][3], lo, hi); o.w = lo + hi + bv.w;
            if (res) {
                float4 rv = *(const float4*)&res[(size_t)row * N + col];
                o.x += rv.x; o.y += rv.y; o.z += rv.z; o.w += rv.w;
            }
            *(float4*)&C[(size_t)row * ldc + col] = o;
        }
    }
}

// ---------------- Attention: one block per (head, window), fp32x2 packed ----------------
// 128 threads, 2 queries/thread, 576 keys in 6 chunks of 96. Online softmax.
__global__ __launch_bounds__(128) void attn_kernel(const float* __restrict__ qkv,
                                                   const float* __restrict__ kv_b,
                                                   float* __restrict__ att) {
    int h  = blockIdx.x;
    int wi = blockIdx.y;
    int wh = wi >> 4, ww = wi & 15;
    int tid = threadIdx.x;
    __shared__ u64 ks2[96][16];   // [key][d-pair], pair 15 zero-padded
    __shared__ u64 vs2[96][16];

    const float scale = 0.18257418583505536f;  // 30^-0.5 (folded into scalar dot)

    int q0i = tid, q1i = tid + 128;
    int tok0 = (wh * 16 + (q0i >> 4)) * 256 + ww * 16 + (q0i & 15);
    int tok1 = (wh * 16 + (q1i >> 4)) * 256 + ww * 16 + (q1i & 15);

    u64 q0p[16], q1p[16], o0p[16], o1p[16];
#pragma unroll
    for (int t = 0; t < 15; t++) {
        q0p[t] = *(const u64*)&qkv[(size_t)tok0 * QKVC + h * HD + 2 * t];
        q1p[t] = *(const u64*)&qkv[(size_t)tok1 * QKVC + h * HD + 2 * t];
    }
    q0p[15] = 0; q1p[15] = 0;
#pragma unroll
    for (int t = 0; t < 16; t++) { o0p[t] = 0; o1p[t] = 0; }
    float m0 = -1e30f, m1 = -1e30f, s0 = 0.f, s1 = 0.f;

    for (int c = 0; c < 6; c++) {
        __syncthreads();
        for (int idx = tid; idx < 96 * 16; idx += 128) {
            int j = idx >> 4, d2 = idx & 15;
            u64 kval = 0, vval = 0;
            if (d2 < 15) {
                int kk = c * 96 + j;               // key index within 24x24 window
                int r = kk / 24, cc = kk - r * 24;
                int gh = wh * 16 - 4 + r, gw = ww * 16 - 4 + cc;
                if ((unsigned)gh < 256u && (unsigned)gw < 256u) {
                    size_t tb = (size_t)(gh * 256 + gw) * QKVC;
                    kval = *(const u64*)&qkv[tb + CDIM + h * HD + 2 * d2];
                    vval = *(const u64*)&qkv[tb + 2 * CDIM + h * HD + 2 * d2];
                } else {
                    kval = *(const u64*)&kv_b[h * HD + 2 * d2];       // zero-pad feat -> kv bias
                    vval = *(const u64*)&kv_b[CDIM + h * HD + 2 * d2];
                }
            }
            ks2[j][d2] = kval;
            vs2[j][d2] = vval;
        }
        __syncthreads();
#pragma unroll 1
        for (int j = 0; j < 96; j++) {
            u64 acc0 = 0, acc1 = 0;
#pragma unroll
            for (int t = 0; t < 16; t++) {
                u64 kd = ks2[j][t];
                fma2(acc0, q0p[t], kd);
                fma2(acc1, q1p[t], kd);
            }
            float lo, hi;
            upk2(acc0, lo, hi); float d0 = (lo + hi) * scale;
            upk2(acc1, lo, hi); float d1 = (lo + hi) * scale;
            if (d0 > m0) {
                float rr = __expf(m0 - d0); m0 = d0; s0 *= rr;
                u64 rp = pk2(rr, rr);
#pragma unroll
                for (int t = 0; t < 16; t++) mul2(o0p[t], rp);
            }
            if (d1 > m1) {
                float rr = __expf(m1 - d1); m1 = d1; s1 *= rr;
                u64 rp = pk2(rr, rr);
#pragma unroll
                for (int t = 0; t < 16; t++) mul2(o1p[t], rp);
            }
            float p0 = __expf(d0 - m0); s0 += p0;
            float p1 = __expf(d1 - m1); s1 += p1;
            u64 p0p = pk2(p0, p0), p1p = pk2(p1, p1);
#pragma unroll
            for (int t = 0; t < 16; t++) {
                u64 vd = vs2[j][t];
                fma2(o0p[t], p0p, vd);
                fma2(o1p[t], p1p, vd);
            }
        }
    }
    float r0 = 1.f / s0, r1 = 1.f / s1;
#pragma unroll
    for (int t = 0; t < 15; t++) {
        float lo, hi;
        upk2(o0p[t], lo, hi);
        *(float2*)&att[(size_t)tok0 * CDIM + h * HD + 2 * t] = make_float2(lo * r0, hi * r0);
        upk2(o1p[t], lo, hi);
        *(float2*)&att[(size_t)tok1 * CDIM + h * HD + 2 * t] = make_float2(lo * r1, hi * r1);
    }
}

extern "C" void kernel_launch(void* const* d_in, const int* in_sizes, int n_in,
                              void* d_out, int out_size) {
    const float* x      = (const float*)d_in[0];
    const float* norm_w = (const float*)d_in[1];
    const float* norm_b = (const float*)d_in[2];
    const float* q_w    = (const float*)d_in[3];
    const float* q_b    = (const float*)d_in[4];
    const float* kv_w   = (const float*)d_in[5];
    const float* kv_b   = (const float*)d_in[6];
    const float* proj_w = (const float*)d_in[7];
    const float* proj_b = (const float*)d_in[8];
    float* out = (float*)d_out;
    (void)in_sizes; (void)n_in; (void)out_size;

    float *xn, *qkv, *att;
    cudaGetSymbolAddress((void**)&xn,  g_xn);
    cudaGetSymbolAddress((void**)&qkv, g_qkv);
    cudaGetSymbolAddress((void**)&att, g_att);

    dim3 gblk(16, 16);

    // 1. LayerNorm
    ln_kernel<<<NTOK / 8, 256>>>(x, norm_w, norm_b, xn);
    // 2. q projection -> qkv[:, 0:180]
    gemm_kernel<<<dim3(3, NTOK / 128), gblk>>>(xn, q_w, q_b, nullptr, qkv, 180, QKVC);
    // 3. kv projection -> qkv[:, 180:540]
    gemm_kernel<<<dim3(6, NTOK / 128), gblk>>>(xn, kv_w, kv_b, nullptr, qkv + CDIM, 360, QKVC);
    // 4. windowed overlapping attention
    attn_kernel<<<dim3(NH, 256), 128>>>(qkv, kv_b, att);
    // 5. output projection + bias + residual -> d_out
    gemm_kernel<<<dim3(3, NTOK / 128), gblk>>>(att, proj_w, proj_b, x, out, 180, CDIM);
}

// round 4
// speedup vs baseline: 3.0774x; 3.0774x over previous
#include <cuda_runtime.h>
#include <cstdint>

#define NTOK 65536
#define CDIM 180
#define NH 6
#define HD 30
#define QKVC 540

// Scratch (device globals — no allocation allowed)
__device__ float g_xn[(size_t)NTOK * CDIM];
__device__ float g_qkv[(size_t)NTOK * QKVC];   // [tok][0:180 q | 180:360 k | 360:540 v]
__device__ float g_att[(size_t)NTOK * CDIM];

__device__ __forceinline__ unsigned f2tf(float f) {
    unsigned r; asm("cvt.rna.tf32.f32 %0, %1;" : "=r"(r) : "f"(f)); return r;
}
__device__ __forceinline__ void mma8(float* d, const unsigned* a, const unsigned* b) {
    asm volatile("mma.sync.aligned.m16n8k8.row.col.f32.tf32.tf32.f32 "
        "{%0,%1,%2,%3},{%4,%5,%6,%7},{%8,%9},{%0,%1,%2,%3};"
        : "+f"(d[0]), "+f"(d[1]), "+f"(d[2]), "+f"(d[3])
        : "r"(a[0]), "r"(a[1]), "r"(a[2]), "r"(a[3]), "r"(b[0]), "r"(b[1]));
}

// ---------------- LayerNorm: one warp per row ----------------
__global__ void ln_kernel(const float* __restrict__ x, const float* __restrict__ w,
                          const float* __restrict__ b, float* __restrict__ out) {
    int row  = blockIdx.x * 8 + (threadIdx.x >> 5);
    int lane = threadIdx.x & 31;
    const float* xr = x + (size_t)row * CDIM;
    float v[6];
    float s = 0.f, s2 = 0.f;
#pragma unroll
    for (int i = 0; i < 6; i++) {
        int d = lane + 32 * i;
        float val = (d < CDIM) ? xr[d] : 0.f;
        v[i] = val; s += val; s2 += val * val;
    }
#pragma unroll
    for (int o = 16; o; o >>= 1) {
        s  += __shfl_xor_sync(0xffffffffu, s, o);
        s2 += __shfl_xor_sync(0xffffffffu, s2, o);
    }
    float mu  = s * (1.f / CDIM);
    float var = s2 * (1.f / CDIM) - mu * mu;
    float rs  = rsqrtf(var + 1e-5f);
    float* orow = out + (size_t)row * CDIM;
#pragma unroll
    for (int i = 0; i < 6; i++) {
        int d = lane + 32 * i;
        if (d < CDIM) orow[d] = (v[i] - mu) * rs * w[d] + b[d];
    }
}

// ---------------- tf32 tensor-core GEMM: C[M,N] = A[M,180]@B[180,N] + bias (+res) ----------------
// Block 128x64, 4 warps (2Mx2N), warp tile 64x32, BK=32 (6 chunks, zero-padded past 180).
__global__ __launch_bounds__(128) void gemm_tc(
    const float* __restrict__ A, const float* __restrict__ B,
    const float* __restrict__ bias, const float* __restrict__ res,
    float* __restrict__ C, int N, int ldc) {
    __shared__ unsigned As[32][136];   // [k][m], stride 136 (8 mod 32) -> conflict-free
    __shared__ unsigned Bs[32][72];    // [k][n], 64 cols + 8 pad (FIX: was [40], OOB)
    int tid = threadIdx.x;
    int lane = tid & 31, wid = tid >> 5;
    int g = lane >> 2, c = lane & 3;
    int m0w = (wid >> 1) * 64, n0w = (wid & 1) * 32;
    int rowbase = blockIdx.y * 128, nbase = blockIdx.x * 64;
    float acc[4][4][4] = {};

    for (int k0 = 0; k0 < 180; k0 += 32) {
        __syncthreads();
        // stage A: thread tid owns row rowbase+tid, 32 k values
        {
            const float* ar = A + (size_t)(rowbase + tid) * 180 + k0;
#pragma unroll
            for (int i = 0; i < 8; i++) {
                int kk = 4 * i;
                float4 v = make_float4(0.f, 0.f, 0.f, 0.f);
                if (k0 + kk < 180) v = *(const float4*)(ar + kk);  // 180%4==0 -> safe
                As[kk + 0][tid] = f2tf(v.x);
                As[kk + 1][tid] = f2tf(v.y);
                As[kk + 2][tid] = f2tf(v.z);
                As[kk + 3][tid] = f2tf(v.w);
            }
        }
        // stage B: 4 passes of 8 k-rows x 64 cols
        {
            int nn = (tid & 15) * 4, kb = tid >> 4;
            int col = nbase + nn;
#pragma unroll
            for (int p = 0; p < 4; p++) {
                int kk = kb + p * 8;
                float4 v = make_float4(0.f, 0.f, 0.f, 0.f);
                if (k0 + kk < 180 && col < N)
                    v = *(const float4*)&B[(size_t)(k0 + kk) * N + col];
                uint4 u;
                u.x = f2tf(v.x); u.y = f2tf(v.y); u.z = f2tf(v.z); u.w = f2tf(v.w);
                *(uint4*)&Bs[kk][nn] = u;
            }
        }
        __syncthreads();
#pragma unroll
        for (int s = 0; s < 4; s++) {
            unsigned a[4][4], b[4][2];
#pragma unroll
            for (int mi = 0; mi < 4; mi++) {
                int m = m0w + 16 * mi + g;
                a[mi][0] = As[8 * s + c][m];
                a[mi][1] = As[8 * s + c][m + 8];
                a[mi][2] = As[8 * s + c + 4][m];
                a[mi][3] = As[8 * s + c + 4][m + 8];
            }
#pragma unroll
            for (int nj = 0; nj < 4; nj++) {
                int n = n0w + 8 * nj + g;
                b[nj][0] = Bs[8 * s + c][n];
                b[nj][1] = Bs[8 * s + c + 4][n];
            }
#pragma unroll
            for (int mi = 0; mi < 4; mi++)
#pragma unroll
                for (int nj = 0; nj < 4; nj++)
                    mma8(acc[mi][nj], a[mi], b[nj]);
        }
    }
    // epilogue: c0,c1 = (row g, cols 2c,2c+1), c2,c3 = row g+8
#pragma unroll
    for (int mi = 0; mi < 4; mi++) {
#pragma unroll
        for (int nj = 0; nj < 4; nj++) {
            int col = nbase + n0w + 8 * nj + 2 * c;
            if (col < N) {
                float bx = bias[col], by = bias[col + 1];
                int r0 = rowbase + m0w + 16 * mi + g;
                float2 o0 = make_float2(acc[mi][nj][0] + bx, acc[mi][nj][1] + by);
                float2 o1 = make_float2(acc[mi][nj][2] + bx, acc[mi][nj][3] + by);
                if (res) {
                    float2 rv0 = *(const float2*)&res[(size_t)r0 * N + col];
                    float2 rv1 = *(const float2*)&res[(size_t)(r0 + 8) * N + col];
                    o0.x += rv0.x; o0.y += rv0.y; o1.x += rv1.x; o1.y += rv1.y;
                }
                *(float2*)&C[(size_t)r0 * ldc + col] = o0;
                *(float2*)&C[(size_t)(r0 + 8) * ldc + col] = o1;
            }
        }
    }
}

// ---------------- Attention: tf32 mma flash kernel ----------------
// Block per (head, window): 8 warps x 32 queries. 18 chunks of 32 keys.
__global__ __launch_bounds__(256) void attn_tc(const float* __restrict__ qkv,
                                               const float* __restrict__ kv_b,
                                               float* __restrict__ att) {
    __shared__ unsigned ks[32][36];        // [key][dim] tf32, stride 36 -> conflict-free frags
    __shared__ unsigned vs[32][36];
    __shared__ unsigned ps[8][32][36];     // per-warp P roundtrip [q][key]
    int h = blockIdx.x;
    int wi = blockIdx.y, wh = wi >> 4, ww = wi & 15;
    int tid = threadIdx.x, lane = tid & 31, w = tid >> 5;
    int g = lane >> 2, c = lane & 3;
    const float scale = 0.18257418583505536f;  // 30^-0.5

    // persistent Q fragments (scale folded in)
    unsigned qf[2][4][4];
#pragma unroll
    for (int mi = 0; mi < 2; mi++) {
        int q0 = w * 32 + mi * 16 + g;
        int q1 = q0 + 8;
        int t0 = (wh * 16 + (q0 >> 4)) * 256 + ww * 16 + (q0 & 15);
        int t1 = (wh * 16 + (q1 >> 4)) * 256 + ww * 16 + (q1 & 15);
        const float* p0 = qkv + (size_t)t0 * QKVC + h * HD;
        const float* p1 = qkv + (size_t)t1 * QKVC + h * HD;
#pragma unroll
        for (int s = 0; s < 4; s++) {
            int d0 = 8 * s + c, d1 = d0 + 4;
            qf[mi][s][0] = f2tf(d0 < HD ? p0[d0] * scale : 0.f);
            qf[mi][s][1] = f2tf(d0 < HD ? p1[d0] * scale : 0.f);
            qf[mi][s][2] = f2tf(d1 < HD ? p0[d1] * scale : 0.f);
            qf[mi][s][3] = f2tf(d1 < HD ? p1[d1] * scale : 0.f);
        }
    }
    float of[2][4][4] = {};
    float mst[2][2] = {{-1e30f, -1e30f}, {-1e30f, -1e30f}};
    float lst[2][2] = {{0.f, 0.f}, {0.f, 0.f}};

    int j = tid >> 3, dbase = (tid & 7) * 4;   // staging: key j, dims dbase..+3
    for (int ci = 0; ci < 18; ci++) {
        __syncthreads();
        // ---- stage 32-key K/V chunk (halo indexing; OOB -> kv bias) ----
        {
            int kk = ci * 32 + j;
            int r = kk / 24, cc = kk - r * 24;
            int gh = wh * 16 - 4 + r, gw = ww * 16 - 4 + cc;
            const float *kp, *vp;
            if ((unsigned)gh < 256u && (unsigned)gw < 256u) {
                size_t tb = (size_t)(gh * 256 + gw) * QKVC;
                kp = qkv + tb + CDIM + h * HD;
                vp = qkv + tb + 2 * CDIM + h * HD;
            } else {
                kp = kv_b + h * HD;
                vp = kv_b + CDIM + h * HD;
            }
            uint4 ku, vu;
            ku.x = f2tf(dbase + 0 < HD ? kp[dbase + 0] : 0.f);
            ku.y = f2tf(dbase + 1 < HD ? kp[dbase + 1] : 0.f);
            ku.z = f2tf(dbase + 2 < HD ? kp[dbase + 2] : 0.f);
            ku.w = f2tf(dbase + 3 < HD ? kp[dbase + 3] : 0.f);
            vu.x = f2tf(dbase + 0 < HD ? vp[dbase + 0] : 0.f);
            vu.y = f2tf(dbase + 1 < HD ? vp[dbase + 1] : 0.f);
            vu.z = f2tf(dbase + 2 < HD ? vp[dbase + 2] : 0.f);
            vu.w = f2tf(dbase + 3 < HD ? vp[dbase + 3] : 0.f);
            *(uint4*)&ks[j][dbase] = ku;
            *(uint4*)&vs[j][dbase] = vu;
        }
        __syncthreads();

        // ---- S = Q @ K^T (32q x 32k per warp) ----
        float sf[2][4][4] = {};
#pragma unroll
        for (int s = 0; s < 4; s++) {
            unsigned b[4][2];
#pragma unroll
            for (int nj = 0; nj < 4; nj++) {
                b[nj][0] = ks[8 * nj + g][8 * s + c];
                b[nj][1] = ks[8 * nj + g][8 * s + c + 4];
            }
#pragma unroll
            for (int mi = 0; mi < 2; mi++)
#pragma unroll
                for (int nj = 0; nj < 4; nj++)
                    mma8(sf[mi][nj], qf[mi][s], b[nj]);
        }

        // ---- online softmax; P -> smem (tf32) ----
#pragma unroll
        for (int mi = 0; mi < 2; mi++) {
            float mx0 = -1e30f, mx1 = -1e30f;
#pragma unroll
            for (int nj = 0; nj < 4; nj++) {
                mx0 = fmaxf(mx0, fmaxf(sf[mi][nj][0], sf[mi][nj][1]));
                mx1 = fmaxf(mx1, fmaxf(sf[mi][nj][2], sf[mi][nj][3]));
            }
            mx0 = fmaxf(mx0, __shfl_xor_sync(0xffffffffu, mx0, 1));
            mx0 = fmaxf(mx0, __shfl_xor_sync(0xffffffffu, mx0, 2));
            mx1 = fmaxf(mx1, __shfl_xor_sync(0xffffffffu, mx1, 1));
            mx1 = fmaxf(mx1, __shfl_xor_sync(0xffffffffu, mx1, 2));
            float mn0 = fmaxf(mst[mi][0], mx0), mn1 = fmaxf(mst[mi][1], mx1);
            float f0 = __expf(mst[mi][0] - mn0), f1 = __expf(mst[mi][1] - mn1);
            mst[mi][0] = mn0; mst[mi][1] = mn1;
#pragma unroll
            for (int dj = 0; dj < 4; dj++) {
                of[mi][dj][0] *= f0; of[mi][dj][1] *= f0;
                of[mi][dj][2] *= f1; of[mi][dj][3] *= f1;
            }
            float rs0 = 0.f, rs1 = 0.f;
#pragma unroll
            for (int nj = 0; nj < 4; nj++) {
                float p0 = __expf(sf[mi][nj][0] - mn0);
                float p1 = __expf(sf[mi][nj][1] - mn0);
                float p2 = __expf(sf[mi][nj][2] - mn1);
                float p3 = __expf(sf[mi][nj][3] - mn1);
                rs0 += p0 + p1; rs1 += p2 + p3;
                uint2 u0, u1;
                u0.x = f2tf(p0); u0.y = f2tf(p1);
                u1.x = f2tf(p2); u1.y = f2tf(p3);
                *(uint2*)&ps[w][16 * mi + g][8 * nj + 2 * c] = u0;
                *(uint2*)&ps[w][16 * mi + g + 8][8 * nj + 2 * c] = u1;
            }
            rs0 += __shfl_xor_sync(0xffffffffu, rs0, 1);
            rs0 += __shfl_xor_sync(0xffffffffu, rs0, 2);
            rs1 += __shfl_xor_sync(0xffffffffu, rs1, 1);
            rs1 += __shfl_xor_sync(0xffffffffu, rs1, 2);
            lst[mi][0] = lst[mi][0] * f0 + rs0;
            lst[mi][1] = lst[mi][1] * f1 + rs1;
        }
        __syncwarp();

        // ---- O += P @ V ----
#pragma unroll
        for (int s = 0; s < 4; s++) {
            unsigned a[2][4], b[4][2];
#pragma unroll
            for (int mi = 0; mi < 2; mi++) {
                a[mi][0] = ps[w][16 * mi + g][8 * s + c];
                a[mi][1] = ps[w][16 * mi + g + 8][8 * s + c];
                a[mi][2] = ps[w][16 * mi + g][8 * s + c + 4];
                a[mi][3] = ps[w][16 * mi + g + 8][8 * s + c + 4];
            }
#pragma unroll
            for (int dj = 0; dj < 4; dj++) {
                b[dj][0] = vs[8 * s + c][8 * dj + g];
                b[dj][1] = vs[8 * s + c + 4][8 * dj + g];
            }
#pragma unroll
            for (int mi = 0; mi < 2; mi++)
#pragma unroll
                for (int dj = 0; dj < 4; dj++)
                    mma8(of[mi][dj], a[mi], b[dj]);
        }
    }

    // ---- normalize + store ----
#pragma unroll
    for (int mi = 0; mi < 2; mi++) {
        float r0 = 1.f / lst[mi][0], r1 = 1.f / lst[mi][1];
        int q0 = w * 32 + mi * 16 + g;
        int q1 = q0 + 8;
        int t0 = (wh * 16 + (q0 >> 4)) * 256 + ww * 16 + (q0 & 15);
        int t1 = (wh * 16 + (q1 >> 4)) * 256 + ww * 16 + (q1 & 15);
        float* o0 = att + (size_t)t0 * CDIM + h * HD;
        float* o1 = att + (size_t)t1 * CDIM + h * HD;
#pragma unroll
        for (int dj = 0; dj < 4; dj++) {
            int d = 8 * dj + 2 * c;
            if (d + 1 < HD) {
                *(float2*)&o0[d] = make_float2(of[mi][dj][0] * r0, of[mi][dj][1] * r0);
                *(float2*)&o1[d] = make_float2(of[mi][dj][2] * r1, of[mi][dj][3] * r1);
            }
        }
    }
}

extern "C" void kernel_launch(void* const* d_in, const int* in_sizes, int n_in,
                              void* d_out, int out_size) {
    const float* x      = (const float*)d_in[0];
    const float* norm_w = (const float*)d_in[1];
    const float* norm_b = (const float*)d_in[2];
    const float* q_w    = (const float*)d_in[3];
    const float* q_b    = (const float*)d_in[4];
    const float* kv_w   = (const float*)d_in[5];
    const float* kv_b   = (const float*)d_in[6];
    const float* proj_w = (const float*)d_in[7];
    const float* proj_b = (const float*)d_in[8];
    float* out = (float*)d_out;
    (void)in_sizes; (void)n_in; (void)out_size;

    float *xn, *qkv, *att;
    cudaGetSymbolAddress((void**)&xn,  g_xn);
    cudaGetSymbolAddress((void**)&qkv, g_qkv);
    cudaGetSymbolAddress((void**)&att, g_att);

    // 1. LayerNorm
    ln_kernel<<<NTOK / 8, 256>>>(x, norm_w, norm_b, xn);
    // 2. q projection -> qkv[:, 0:180]
    gemm_tc<<<dim3(3, NTOK / 128), 128>>>(xn, q_w, q_b, nullptr, qkv, 180, QKVC);
    // 3. kv projection -> qkv[:, 180:540]
    gemm_tc<<<dim3(6, NTOK / 128), 128>>>(xn, kv_w, kv_b, nullptr, qkv + CDIM, 360, QKVC);
    // 4. windowed overlapping attention (tensor cores)
    attn_tc<<<dim3(NH, 256), 256>>>(qkv, kv_b, att);
    // 5. output projection + bias + residual -> d_out
    gemm_tc<<<dim3(3, NTOK / 128), 128>>>(att, proj_w, proj_b, x, out, 180, CDIM);
}

// round 5
// speedup vs baseline: 3.1973x; 1.0389x over previous
#include <cuda_runtime.h>
#include <cstdint>

#define NTOK 65536
#define CDIM 180
#define NH 6
#define HD 30
#define QKVC 540

// Scratch (device globals — no allocation allowed)
__device__ float g_xn[(size_t)NTOK * CDIM];
__device__ float g_qkv[(size_t)NTOK * QKVC];   // [tok][0:180 q | 180:360 k | 360:540 v]
__device__ float g_att[(size_t)NTOK * CDIM];

__device__ __forceinline__ void mma8(float* d, const unsigned* a, const unsigned* b) {
    asm volatile("mma.sync.aligned.m16n8k8.row.col.f32.tf32.tf32.f32 "
        "{%0,%1,%2,%3},{%4,%5,%6,%7},{%8,%9},{%0,%1,%2,%3};"
        : "+f"(d[0]), "+f"(d[1]), "+f"(d[2]), "+f"(d[3])
        : "r"(a[0]), "r"(a[1]), "r"(a[2]), "r"(a[3]), "r"(b[0]), "r"(b[1]));
}
__device__ __forceinline__ void ldsm4(unsigned* r, unsigned addr) {
    asm volatile("ldmatrix.sync.aligned.m8n8.x4.shared.b16 {%0,%1,%2,%3}, [%4];"
        : "=r"(r[0]), "=r"(r[1]), "=r"(r[2]), "=r"(r[3]) : "r"(addr));
}
__device__ __forceinline__ float ex2f(float x) {
    float y; asm("ex2.approx.f32 %0, %1;" : "=f"(y) : "f"(x)); return y;
}

// ---------------- LayerNorm: one warp per row ----------------
__global__ void ln_kernel(const float* __restrict__ x, const float* __restrict__ w,
                          const float* __restrict__ b, float* __restrict__ out) {
    int row  = blockIdx.x * 8 + (threadIdx.x >> 5);
    int lane = threadIdx.x & 31;
    const float* xr = x + (size_t)row * CDIM;
    float v[6];
    float s = 0.f, s2 = 0.f;
#pragma unroll
    for (int i = 0; i < 6; i++) {
        int d = lane + 32 * i;
        float val = (d < CDIM) ? xr[d] : 0.f;
        v[i] = val; s += val; s2 += val * val;
    }
#pragma unroll
    for (int o = 16; o; o >>= 1) {
        s  += __shfl_xor_sync(0xffffffffu, s, o);
        s2 += __shfl_xor_sync(0xffffffffu, s2, o);
    }
    float mu  = s * (1.f / CDIM);
    float var = s2 * (1.f / CDIM) - mu * mu;
    float rs  = rsqrtf(var + 1e-5f);
    float* orow = out + (size_t)row * CDIM;
#pragma unroll
    for (int i = 0; i < 6; i++) {
        int d = lane + 32 * i;
        if (d < CDIM) orow[d] = (v[i] - mu) * rs * w[d] + b[d];
    }
}

// ---------------- tf32 tensor-core GEMM via ldmatrix ----------------
// Block 128x64, 4 warps (2Mx2N), warp tile 64x32, BK=32. A row-major, B transposed
// in smem (both stride 36 words == 4 mod 32 -> conflict-free LDSM).
__global__ __launch_bounds__(128) void gemm_tc(
    const float* __restrict__ A, const float* __restrict__ B,
    const float* __restrict__ bias, const float* __restrict__ res,
    float* __restrict__ C, int N, int ldc) {
    __shared__ float As[128][36];   // [m][k]
    __shared__ float BsT[64][36];   // [n][k]
    int tid = threadIdx.x;
    int lane = tid & 31, wid = tid >> 5;
    int lr = lane & 7, grp = lane >> 3;
    int g = lane >> 2, c = lane & 3;
    int m0w = (wid >> 1) * 64, n0w = (wid & 1) * 32;
    int rowbase = blockIdx.y * 128, nbase = blockIdx.x * 64;
    float acc[4][4][4] = {};
    unsigned as_base = (unsigned)__cvta_generic_to_shared(&As[0][0]);
    unsigned bs_base = (unsigned)__cvta_generic_to_shared(&BsT[0][0]);

    int bn = tid & 63, bk0 = (tid >> 6) * 4;
    int bcol = nbase + bn;

    for (int k0 = 0; k0 < 180; k0 += 32) {
        __syncthreads();
        // stage A: thread owns row rowbase+tid (raw f32; mma truncates to tf32)
        {
            const float* ar = A + (size_t)(rowbase + tid) * 180 + k0;
#pragma unroll
            for (int i = 0; i < 8; i++) {
                int kk = 4 * i;
                float4 v = (k0 + kk < 180) ? *(const float4*)(ar + kk)
                                           : make_float4(0.f, 0.f, 0.f, 0.f);
                *(float4*)&As[tid][kk] = v;
            }
        }
        // stage B transposed: thread owns col bcol, 4 k-groups of 4
#pragma unroll
        for (int p = 0; p < 4; p++) {
            int kk = bk0 + 8 * p;
            float4 v;
            v.x = (k0 + kk + 0 < 180 && bcol < N) ? B[(size_t)(k0 + kk + 0) * N + bcol] : 0.f;
            v.y = (k0 + kk + 1 < 180 && bcol < N) ? B[(size_t)(k0 + kk + 1) * N + bcol] : 0.f;
            v.z = (k0 + kk + 2 < 180 && bcol < N) ? B[(size_t)(k0 + kk + 2) * N + bcol] : 0.f;
            v.w = (k0 + kk + 3 < 180 && bcol < N) ? B[(size_t)(k0 + kk + 3) * N + bcol] : 0.f;
            *(float4*)&BsT[bn][kk] = v;
        }
        __syncthreads();
#pragma unroll
        for (int s = 0; s < 4; s++) {
            unsigned a[4][4], b[4][2];
#pragma unroll
            for (int mi = 0; mi < 4; mi++) {
                unsigned addr = as_base +
                    (((m0w + 16 * mi + 8 * (grp & 1) + lr) * 36 + 8 * s + 4 * (grp >> 1)) << 2);
                ldsm4(a[mi], addr);
            }
#pragma unroll
            for (int pj = 0; pj < 2; pj++) {
                unsigned t[4];
                unsigned addr = bs_base +
                    (((n0w + 8 * (2 * pj + (grp >> 1)) + lr) * 36 + 8 * s + 4 * (grp & 1)) << 2);
                ldsm4(t, addr);
                b[2 * pj][0] = t[0]; b[2 * pj][1] = t[1];
                b[2 * pj + 1][0] = t[2]; b[2 * pj + 1][1] = t[3];
            }
#pragma unroll
            for (int mi = 0; mi < 4; mi++)
#pragma unroll
                for (int nj = 0; nj < 4; nj++)
                    mma8(acc[mi][nj], a[mi], b[nj]);
        }
    }
    // epilogue
#pragma unroll
    for (int mi = 0; mi < 4; mi++) {
#pragma unroll
        for (int nj = 0; nj < 4; nj++) {
            int col = nbase + n0w + 8 * nj + 2 * c;
            if (col < N) {
                float bx = bias[col], by = bias[col + 1];
                int r0 = rowbase + m0w + 16 * mi + g;
                float2 o0 = make_float2(acc[mi][nj][0] + bx, acc[mi][nj][1] + by);
                float2 o1 = make_float2(acc[mi][nj][2] + bx, acc[mi][nj][3] + by);
                if (res) {
                    float2 rv0 = *(const float2*)&res[(size_t)r0 * N + col];
                    float2 rv1 = *(const float2*)&res[(size_t)(r0 + 8) * N + col];
                    o0.x += rv0.x; o0.y += rv0.y; o1.x += rv1.x; o1.y += rv1.y;
                }
                *(float2*)&C[(size_t)r0 * ldc + col] = o0;
                *(float2*)&C[(size_t)(r0 + 8) * ldc + col] = o1;
            }
        }
    }
}

// ---------------- Attention: tf32 mma flash kernel, ldmatrix fragments ----------------
// Block per (head, window): 8 warps x 32 queries. 18 chunks of 32 keys.
__global__ __launch_bounds__(256) void attn_tc(const float* __restrict__ qkv,
                                               const float* __restrict__ kv_b,
                                               float* __restrict__ att) {
    __shared__ float ks[32][36];     // [key][dim]
    __shared__ float vsT[32][36];    // [dim][key] (transposed for PV B-frags)
    __shared__ float ps[8][32][36];  // per-warp P [q][key]
    int h = blockIdx.x;
    int wi = blockIdx.y, wh = wi >> 4, ww = wi & 15;
    int tid = threadIdx.x, lane = tid & 31, w = tid >> 5;
    int g = lane >> 2, c = lane & 3;
    int lr = lane & 7, grp = lane >> 3;
    const float qscale = 0.18257418583505536f * 1.44269504088896f;  // 30^-.5 * log2(e)

    unsigned ks_base = (unsigned)__cvta_generic_to_shared(&ks[0][0]);
    unsigned vs_base = (unsigned)__cvta_generic_to_shared(&vsT[0][0]);
    unsigned ps_base = (unsigned)__cvta_generic_to_shared(&ps[w][0][0]);

    // persistent Q fragments (scale*log2e folded in; raw f32 -> tf32 truncation in mma)
    unsigned qf[2][4][4];
#pragma unroll
    for (int mi = 0; mi < 2; mi++) {
        int q0 = w * 32 + mi * 16 + g;
        int q1 = q0 + 8;
        int t0 = (wh * 16 + (q0 >> 4)) * 256 + ww * 16 + (q0 & 15);
        int t1 = (wh * 16 + (q1 >> 4)) * 256 + ww * 16 + (q1 & 15);
        const float* p0 = qkv + (size_t)t0 * QKVC + h * HD;
        const float* p1 = qkv + (size_t)t1 * QKVC + h * HD;
#pragma unroll
        for (int s = 0; s < 4; s++) {
            int d0 = 8 * s + c, d1 = d0 + 4;
            qf[mi][s][0] = __float_as_uint(d0 < HD ? p0[d0] * qscale : 0.f);
            qf[mi][s][1] = __float_as_uint(d0 < HD ? p1[d0] * qscale : 0.f);
            qf[mi][s][2] = __float_as_uint(d1 < HD ? p0[d1] * qscale : 0.f);
            qf[mi][s][3] = __float_as_uint(d1 < HD ? p1[d1] * qscale : 0.f);
        }
    }
    float of[2][4][4] = {};
    float mst[2][2] = {{-1e30f, -1e30f}, {-1e30f, -1e30f}};
    float lst[2][2] = {{0.f, 0.f}, {0.f, 0.f}};

    int j = tid >> 3, dbase = (tid & 7) * 4;   // staging: key j, dims dbase..+3
    for (int ci = 0; ci < 18; ci++) {
        __syncthreads();
        // ---- stage 32-key K/V chunk (halo indexing; OOB -> kv bias) ----
        {
            int kk = ci * 32 + j;
            int r = kk / 24, cc = kk - r * 24;
            int gh = wh * 16 - 4 + r, gw = ww * 16 - 4 + cc;
            const float *kp, *vp;
            if ((unsigned)gh < 256u && (unsigned)gw < 256u) {
                size_t tb = (size_t)(gh * 256 + gw) * QKVC;
                kp = qkv + tb + CDIM + h * HD;
                vp = qkv + tb + 2 * CDIM + h * HD;
            } else {
                kp = kv_b + h * HD;
                vp = kv_b + CDIM + h * HD;
            }
            float4 kv4, vv4;
            if (dbase < 28) {  // scalar loads (h*HD breaks 16B alignment)
                kv4 = make_float4(kp[dbase], kp[dbase + 1], kp[dbase + 2], kp[dbase + 3]);
                vv4 = make_float4(vp[dbase], vp[dbase + 1], vp[dbase + 2], vp[dbase + 3]);
            } else {           // dims 28,29 real; 30,31 zero-pad
                kv4 = make_float4(kp[28], kp[29], 0.f, 0.f);
                vv4 = make_float4(vp[28], vp[29], 0.f, 0.f);
            }
            *(float4*)&ks[j][dbase] = kv4;
            vsT[dbase + 0][j] = vv4.x;
            vsT[dbase + 1][j] = vv4.y;
            vsT[dbase + 2][j] = vv4.z;
            vsT[dbase + 3][j] = vv4.w;
        }
        __syncthreads();

        // ---- S = Q @ K^T (32q x 32k per warp) ----
        float sf[2][4][4] = {};
#pragma unroll
        for (int s = 0; s < 4; s++) {
            unsigned b[4][2];
#pragma unroll
            for (int pj = 0; pj < 2; pj++) {
                unsigned t[4];
                unsigned addr = ks_base +
                    (((8 * (2 * pj + (grp >> 1)) + lr) * 36 + 8 * s + 4 * (grp & 1)) << 2);
                ldsm4(t, addr);
                b[2 * pj][0] = t[0]; b[2 * pj][1] = t[1];
                b[2 * pj + 1][0] = t[2]; b[2 * pj + 1][1] = t[3];
            }
#pragma unroll
            for (int mi = 0; mi < 2; mi++)
#pragma unroll
                for (int nj = 0; nj < 4; nj++)
                    mma8(sf[mi][nj], qf[mi][s], b[nj]);
        }

        // ---- online softmax (base-2 domain); P -> smem (raw f32) ----
#pragma unroll
        for (int mi = 0; mi < 2; mi++) {
            float mx0 = -1e30f, mx1 = -1e30f;
#pragma unroll
            for (int nj = 0; nj < 4; nj++) {
                mx0 = fmaxf(mx0, fmaxf(sf[mi][nj][0], sf[mi][nj][1]));
                mx1 = fmaxf(mx1, fmaxf(sf[mi][nj][2], sf[mi][nj][3]));
            }
            mx0 = fmaxf(mx0, __shfl_xor_sync(0xffffffffu, mx0, 1));
            mx0 = fmaxf(mx0, __shfl_xor_sync(0xffffffffu, mx0, 2));
            mx1 = fmaxf(mx1, __shfl_xor_sync(0xffffffffu, mx1, 1));
            mx1 = fmaxf(mx1, __shfl_xor_sync(0xffffffffu, mx1, 2));
            float mn0 = fmaxf(mst[mi][0], mx0), mn1 = fmaxf(mst[mi][1], mx1);
            float f0 = ex2f(mst[mi][0] - mn0), f1 = ex2f(mst[mi][1] - mn1);
            mst[mi][0] = mn0; mst[mi][1] = mn1;
#pragma unroll
            for (int dj = 0; dj < 4; dj++) {
                of[mi][dj][0] *= f0; of[mi][dj][1] *= f0;
                of[mi][dj][2] *= f1; of[mi][dj][3] *= f1;
            }
            float rs0 = 0.f, rs1 = 0.f;
#pragma unroll
            for (int nj = 0; nj < 4; nj++) {
                float p0 = ex2f(sf[mi][nj][0] - mn0);
                float p1 = ex2f(sf[mi][nj][1] - mn0);
                float p2 = ex2f(sf[mi][nj][2] - mn1);
                float p3 = ex2f(sf[mi][nj][3] - mn1);
                rs0 += p0 + p1; rs1 += p2 + p3;
                *(float2*)&ps[w][16 * mi + g][8 * nj + 2 * c] = make_float2(p0, p1);
                *(float2*)&ps[w][16 * mi + g + 8][8 * nj + 2 * c] = make_float2(p2, p3);
            }
            rs0 += __shfl_xor_sync(0xffffffffu, rs0, 1);
            rs0 += __shfl_xor_sync(0xffffffffu, rs0, 2);
            rs1 += __shfl_xor_sync(0xffffffffu, rs1, 1);
            rs1 += __shfl_xor_sync(0xffffffffu, rs1, 2);
            lst[mi][0] = lst[mi][0] * f0 + rs0;
            lst[mi][1] = lst[mi][1] * f1 + rs1;
        }
        __syncwarp();

        // ---- O += P @ V ----
#pragma unroll
        for (int s = 0; s < 4; s++) {
            unsigned a[2][4], b[4][2];
#pragma unroll
            for (int mi = 0; mi < 2; mi++) {
                unsigned addr = ps_base +
                    (((16 * mi + 8 * (grp & 1) + lr) * 36 + 8 * s + 4 * (grp >> 1)) << 2);
                ldsm4(a[mi], addr);
            }
#pragma unroll
            for (int pj = 0; pj < 2; pj++) {
                unsigned t[4];
                unsigned addr = vs_base +
                    (((8 * (2 * pj + (grp >> 1)) + lr) * 36 + 8 * s + 4 * (grp & 1)) << 2);
                ldsm4(t, addr);
                b[2 * pj][0] = t[0]; b[2 * pj][1] = t[1];
                b[2 * pj + 1][0] = t[2]; b[2 * pj + 1][1] = t[3];
            }
#pragma unroll
            for (int mi = 0; mi < 2; mi++)
#pragma unroll
                for (int dj = 0; dj < 4; dj++)
                    mma8(of[mi][dj], a[mi], b[dj]);
        }
    }

    // ---- normalize + store ----
#pragma unroll
    for (int mi = 0; mi < 2; mi++) {
        float r0 = 1.f / lst[mi][0], r1 = 1.f / lst[mi][1];
        int q0 = w * 32 + mi * 16 + g;
        int q1 = q0 + 8;
        int t0 = (wh * 16 + (q0 >> 4)) * 256 + ww * 16 + (q0 & 15);
        int t1 = (wh * 16 + (q1 >> 4)) * 256 + ww * 16 + (q1 & 15);
        float* o0 = att + (size_t)t0 * CDIM + h * HD;
        float* o1 = att + (size_t)t1 * CDIM + h * HD;
#pragma unroll
        for (int dj = 0; dj < 4; dj++) {
            int d = 8 * dj + 2 * c;
            if (d + 1 < HD) {
                *(float2*)&o0[d] = make_float2(of[mi][dj][0] * r0, of[mi][dj][1] * r0);
                *(float2*)&o1[d] = make_float2(of[mi][dj][2] * r1, of[mi][dj][3] * r1);
            }
        }
    }
}

extern "C" void kernel_launch(void* const* d_in, const int* in_sizes, int n_in,
                              void* d_out, int out_size) {
    const float* x      = (const float*)d_in[0];
    const float* norm_w = (const float*)d_in[1];
    const float* norm_b = (const float*)d_in[2];
    const float* q_w    = (const float*)d_in[3];
    const float* q_b    = (const float*)d_in[4];
    const float* kv_w   = (const float*)d_in[5];
    const float* kv_b   = (const float*)d_in[6];
    const float* proj_w = (const float*)d_in[7];
    const float* proj_b = (const float*)d_in[8];
    float* out = (float*)d_out;
    (void)in_sizes; (void)n_in; (void)out_size;

    float *xn, *qkv, *att;
    cudaGetSymbolAddress((void**)&xn,  g_xn);
    cudaGetSymbolAddress((void**)&qkv, g_qkv);
    cudaGetSymbolAddress((void**)&att, g_att);

    // 1. LayerNorm
    ln_kernel<<<NTOK / 8, 256>>>(x, norm_w, norm_b, xn);
    // 2. q projection -> qkv[:, 0:180]
    gemm_tc<<<dim3(3, NTOK / 128), 128>>>(xn, q_w, q_b, nullptr, qkv, 180, QKVC);
    // 3. kv projection -> qkv[:, 180:540]
    gemm_tc<<<dim3(6, NTOK / 128), 128>>>(xn, kv_w, kv_b, nullptr, qkv + CDIM, 360, QKVC);
    // 4. windowed overlapping attention (tensor cores)
    attn_tc<<<dim3(NH, 256), 256>>>(qkv, kv_b, att);
    // 5. output projection + bias + residual -> d_out
    gemm_tc<<<dim3(3, NTOK / 128), 128>>>(att, proj_w, proj_b, x, out, 180, CDIM);
}